// round 1
// baseline (speedup 1.0000x reference)
#include <cuda_runtime.h>
#include <cstdint>
#include <cstddef>

// Problem constants
#define BDIM 8
#define DDIM 256
#define TDIM 8192
#define NQ 8
#define BINS 1024
#define TT 64                      // tokens per CTA
#define NB 64                      // bins per chunk
#define NCHUNK (BINS / NB)         // 16
#define RS 260                     // padded row stride (floats); 260*4=1040B, 1040%128=16 -> good bank spread
#define NTILE ((BDIM * TDIM) / TT) // 1024 CTAs
#define QELEMS (BDIM * DDIM * TDIM)        // 16777216
#define CELEMS (NQ * BDIM * TDIM)          // 524288
#define SMEM_BYTES ((3 * TT * RS) * 4 + 256 + 64) // 200000

__device__ float  g_cbsq[NQ * BINS];
__device__ double g_losspart[NTILE];

// ---------------------------------------------------------------------------
// Precompute ||c||^2 per codebook row. One warp per bin.
// ---------------------------------------------------------------------------
__global__ void cbsq_kernel(const float* __restrict__ cbs) {
    int gid  = blockIdx.x * blockDim.x + threadIdx.x;
    int w    = gid >> 5;          // bin id in [0, NQ*BINS)
    int lane = gid & 31;
    const float* row = cbs + (size_t)w * DDIM;
    float s = 0.f;
#pragma unroll
    for (int k = 0; k < DDIM; k += 32) {
        float v = row[k + lane];
        s = fmaf(v, v, s);
    }
#pragma unroll
    for (int o = 16; o; o >>= 1) s += __shfl_xor_sync(0xffffffffu, s, o);
    if (lane == 0) g_cbsq[w] = s;
}

// ---------------------------------------------------------------------------
// Async prefetch of one 64-bin codebook chunk into SMEM (row-padded to RS).
// ---------------------------------------------------------------------------
__device__ __forceinline__ void prefetch_chunk(const float* __restrict__ cbs,
                                               int g, float* __restrict__ sCbuf,
                                               int tid) {
    int s = g >> 4, c = g & 15;
    const float* src = cbs + (size_t)(s * BINS + c * NB) * DDIM;
    unsigned dstbase = (unsigned)__cvta_generic_to_shared(sCbuf);
#pragma unroll
    for (int it = 0; it < 16; ++it) {
        int f   = tid + it * 256;   // float4 index, 0..4095
        int row = f >> 6;           // bin row 0..63
        int c4  = f & 63;           // float4 within row
        unsigned     dst = dstbase + (unsigned)((row * RS + c4 * 4) * 4);
        const float* gp  = src + row * DDIM + c4 * 4;
        asm volatile("cp.async.cg.shared.global [%0], [%1], 16;\n" ::"r"(dst), "l"(gp));
    }
    asm volatile("cp.async.commit_group;\n");
}

#define FMA2(d, a, b) \
    asm volatile("fma.rn.f32x2 %0, %1, %2, %0;" : "+l"(d) : "l"(a), "l"(b))

// ---------------------------------------------------------------------------
// Fused RVQ kernel: one CTA = 64 tokens, residual resident in SMEM across all
// 8 stages. Per stage: stream 16 codebook chunks (double-buffered cp.async),
// f32x2 register-tiled GEMM (4 tokens x 4 bins per thread), running argmin,
// lexicographic cross-thread reduce, residual update, code emit.
// ---------------------------------------------------------------------------
__global__ __launch_bounds__(256, 1) void rvq_main(const float* __restrict__ x,
                                                   const float* __restrict__ cbs,
                                                   float* __restrict__ out) {
    extern __shared__ float sm[];
    float* sR    = sm;                               // [TT][RS] residual, t-major
    float* sC0   = sm + TT * RS;                     // chunk buffer 0 [NB][RS]
    float* sC1   = sm + 2 * TT * RS;                 // chunk buffer 1
    int*   sIdx  = (int*)(sm + 3 * TT * RS);         // [TT] chosen bins
    double* sWD  = (double*)((char*)sm + (3 * TT * RS) * 4 + 256); // [8] warp loss

    const int tid = threadIdx.x;
    const int tx  = tid & 15;   // bin group: bins {tx, tx+16, tx+32, tx+48} of chunk
    const int ty  = tid >> 4;   // token group: tokens ty*4 .. ty*4+3
    const int b   = blockIdx.x >> 7;
    const int t0  = (blockIdx.x & 127) * TT;

    float* out_q = out;
    float* out_c = out + QELEMS;

    // ---- prologue: load + transpose x tile into sR[t][k] ----
#pragma unroll
    for (int it = 0; it < 16; ++it) {
        int f  = tid + it * 256;
        int k  = f >> 4;
        int t4 = f & 15;
        float4 v = *(const float4*)(x + (size_t)(b * DDIM + k) * TDIM + t0 + t4 * 4);
        int tl = t4 * 4;
        sR[(tl + 0) * RS + k] = v.x;
        sR[(tl + 1) * RS + k] = v.y;
        sR[(tl + 2) * RS + k] = v.z;
        sR[(tl + 3) * RS + k] = v.w;
    }
    prefetch_chunk(cbs, 0, sC0, tid);

    double lossLocal = 0.0;
    const float* Rb = sR + (ty * 4) * RS;

    for (int s = 0; s < NQ; ++s) {
        float bestd[4];
        int   besti[4];
#pragma unroll
        for (int i = 0; i < 4; ++i) { bestd[i] = 3.4e38f; besti[i] = 0; }

        for (int c = 0; c < NCHUNK; ++c) {
            int g = s * NCHUNK + c;
            __syncthreads();   // previous chunk's compute done -> safe to refill other buffer
            if (g + 1 < NQ * NCHUNK) {
                prefetch_chunk(cbs, g + 1, ((g + 1) & 1) ? sC1 : sC0, tid);
                asm volatile("cp.async.wait_group 1;\n");
            } else {
                asm volatile("cp.async.wait_group 0;\n");
            }
            __syncthreads();   // chunk g data visible to all threads

            const float* Cb = ((g & 1) ? sC1 : sC0) + tx * RS;

            ulonglong2 acc[4][4];
#pragma unroll
            for (int i = 0; i < 4; ++i)
#pragma unroll
                for (int j = 0; j < 4; ++j) { acc[i][j].x = 0ull; acc[i][j].y = 0ull; }

#pragma unroll 4
            for (int k4 = 0; k4 < DDIM; k4 += 4) {
                ulonglong2 r[4], cc[4];
#pragma unroll
                for (int i = 0; i < 4; ++i)
                    r[i] = *(const ulonglong2*)(Rb + i * RS + k4);
#pragma unroll
                for (int j = 0; j < 4; ++j)
                    cc[j] = *(const ulonglong2*)(Cb + (j * 16) * RS + k4);
#pragma unroll
                for (int i = 0; i < 4; ++i)
#pragma unroll
                    for (int j = 0; j < 4; ++j) {
                        FMA2(acc[i][j].x, r[i].x, cc[j].x);
                        FMA2(acc[i][j].y, r[i].y, cc[j].y);
                    }
            }

            // distances + running argmin (bins ascending within thread -> first-min wins)
            int binbase = c * NB + tx;
#pragma unroll
            for (int i = 0; i < 4; ++i)
#pragma unroll
                for (int j = 0; j < 4; ++j) {
                    float ax, ay, bx, by;
                    asm("mov.b64 {%0,%1}, %2;" : "=f"(ax), "=f"(ay) : "l"(acc[i][j].x));
                    asm("mov.b64 {%0,%1}, %2;" : "=f"(bx), "=f"(by) : "l"(acc[i][j].y));
                    float dot = (ax + ay) + (bx + by);
                    int   bin = binbase + j * 16;
                    float dist = fmaf(-2.f, dot, g_cbsq[s * BINS + bin]);
                    if (dist < bestd[i]) { bestd[i] = dist; besti[i] = bin; }
                }
        }

        // ---- reduce argmin across the 16 tx lanes (lexicographic: dist, then idx) ----
#pragma unroll
        for (int o = 1; o < 16; o <<= 1) {
#pragma unroll
            for (int i = 0; i < 4; ++i) {
                float od = __shfl_xor_sync(0xffffffffu, bestd[i], o);
                int   oi = __shfl_xor_sync(0xffffffffu, besti[i], o);
                if (od < bestd[i] || (od == bestd[i] && oi < besti[i])) {
                    bestd[i] = od;
                    besti[i] = oi;
                }
            }
        }
        if (tx == 0) {
#pragma unroll
            for (int i = 0; i < 4; ++i) sIdx[ty * 4 + i] = besti[i];
        }
        __syncthreads();

        // codes output (as float, per assumed concat layout [NQ, B, T])
        if (tid < TT)
            out_c[(size_t)(s * BDIM + b) * TDIM + t0 + tid] = (float)sIdx[tid];

        // ---- residual update + commitment loss: r -= cb[idx]; loss += r_new^2 ----
        {
            int t  = tid >> 2;
            int ko = (tid & 3) * 64;
            int idx = sIdx[t];
            const float4* cv = (const float4*)(cbs + (size_t)(s * BINS + idx) * DDIM + ko);
            float* rp = sR + t * RS + ko;
            float  lsum = 0.f;
#pragma unroll
            for (int q = 0; q < 16; ++q) {
                float4 v  = cv[q];
                float a0 = rp[q * 4 + 0] - v.x;
                float a1 = rp[q * 4 + 1] - v.y;
                float a2 = rp[q * 4 + 2] - v.z;
                float a3 = rp[q * 4 + 3] - v.w;
                rp[q * 4 + 0] = a0; rp[q * 4 + 1] = a1;
                rp[q * 4 + 2] = a2; rp[q * 4 + 3] = a3;
                lsum += a0 * a0 + a1 * a1 + a2 * a2 + a3 * a3;
            }
            lossLocal += (double)lsum;
        }
        // next chunk loop's first __syncthreads covers sR visibility
    }
    __syncthreads();

    // ---- epilogue: quantized = x - final residual, transposed back to [B,D,T] ----
#pragma unroll
    for (int it = 0; it < 16; ++it) {
        int f  = tid + it * 256;
        int k  = f >> 4;
        int t4 = f & 15;
        const float4 v = *(const float4*)(x + (size_t)(b * DDIM + k) * TDIM + t0 + t4 * 4);
        int tl = t4 * 4;
        float4 o;
        o.x = v.x - sR[(tl + 0) * RS + k];
        o.y = v.y - sR[(tl + 1) * RS + k];
        o.z = v.z - sR[(tl + 2) * RS + k];
        o.w = v.w - sR[(tl + 3) * RS + k];
        *(float4*)(out_q + (size_t)(b * DDIM + k) * TDIM + t0 + t4 * 4) = o;
    }

    // ---- deterministic per-CTA loss partial ----
    int lane = tid & 31, w = tid >> 5;
#pragma unroll
    for (int o = 16; o; o >>= 1) lossLocal += __shfl_down_sync(0xffffffffu, lossLocal, o);
    if (lane == 0) sWD[w] = lossLocal;
    __syncthreads();
    if (tid == 0) {
        double t = 0.0;
        for (int i = 0; i < 8; ++i) t += sWD[i];
        g_losspart[blockIdx.x] = t;
    }
}

// ---------------------------------------------------------------------------
// Final scalars: bandwidth + commit loss (deterministic fixed-order sum).
// ---------------------------------------------------------------------------
__global__ void finalize_kernel(const int* __restrict__ srp, float* __restrict__ out) {
    int lane = threadIdx.x;
    double s = 0.0;
    for (int i = lane; i < NTILE; i += 32) s += g_losspart[i];
#pragma unroll
    for (int o = 16; o; o >>= 1) s += __shfl_down_sync(0xffffffffu, s, o);
    if (lane == 0) {
        int   iv = *srp;
        float fv = __int_as_float(iv);
        double sr = (iv > 0 && iv < 100000000) ? (double)iv : (double)fv;
        out[QELEMS + CELEMS]     = (float)((double)NQ * 10.0 * sr / 1000.0); // n_q*log2(1024)*sr/1000
        out[QELEMS + CELEMS + 1] = (float)(s / (4.0 * (double)NQ * (double)QELEMS));
    }
}

// ---------------------------------------------------------------------------
extern "C" void kernel_launch(void* const* d_in, const int* in_sizes, int n_in,
                              void* d_out, int out_size) {
    const float* x   = nullptr;
    const float* cbs = nullptr;
    const int*   srp = nullptr;
    for (int i = 0; i < n_in; ++i) {
        if (in_sizes[i] == QELEMS)                x   = (const float*)d_in[i];
        else if (in_sizes[i] == NQ * BINS * DDIM) cbs = (const float*)d_in[i];
        else                                      srp = (const int*)d_in[i];
    }
    float* out = (float*)d_out;

    cudaFuncSetAttribute(rvq_main, cudaFuncAttributeMaxDynamicSharedMemorySize, SMEM_BYTES);

    cbsq_kernel<<<(NQ * BINS * 32) / 256, 256>>>(cbs);
    rvq_main<<<NTILE, 256, SMEM_BYTES>>>(x, cbs, out);
    finalize_kernel<<<1, 32>>>(srp, out);
}